// round 2
// baseline (speedup 1.0000x reference)
#include <cuda_runtime.h>
#include <math.h>

#define DIM 256
#define NH 4
#define HC 64
#define NTOK 49
#define NB 4096

// Standardized weights/biases (written once per launch by std_kernel).
__device__ __align__(16) float g_W[5][DIM * DIM];
__device__ float g_b[5][DIM];

// ---------------------------------------------------------------------------
// Kernel 0: weight standardization.
//   blocks [0, 5*256): one block per (matrix m, row): per-head (64-col group)
//   normalize: (w - mean)/(std * sqrt(256)).
//   blocks [1280, 1285): biases, same per-head normalization.
// ---------------------------------------------------------------------------
__global__ __launch_bounds__(256) void std_kernel(
    const float* __restrict__ qw, const float* __restrict__ qb,
    const float* __restrict__ kw, const float* __restrict__ kb,
    const float* __restrict__ vw, const float* __restrict__ vb,
    const float* __restrict__ fiw, const float* __restrict__ fib,
    const float* __restrict__ fow, const float* __restrict__ fob)
{
    const float* wptr[5] = {qw, kw, vw, fiw, fow};
    const float* bptr[5] = {qb, kb, vb, fib, fob};

    __shared__ float s_sum[8];
    __shared__ float s_sq[8];

    int bx = blockIdx.x;
    int t  = threadIdx.x;

    float val;
    float* outp;
    if (bx < 5 * DIM) {
        int m = bx >> 8;
        int row = bx & 255;
        val  = wptr[m][row * DIM + t];
        outp = &g_W[m][row * DIM + t];
    } else {
        int m = bx - 5 * DIM;
        val  = bptr[m][t];
        outp = &g_b[m][t];
    }

    float s = val, q = val * val;
    #pragma unroll
    for (int o = 16; o > 0; o >>= 1) {
        s += __shfl_xor_sync(0xFFFFFFFFu, s, o);
        q += __shfl_xor_sync(0xFFFFFFFFu, q, o);
    }
    int w = t >> 5;
    if ((t & 31) == 0) { s_sum[w] = s; s_sq[w] = q; }
    __syncthreads();

    int h = t >> 6;  // head = group of 64 cols = warps 2h, 2h+1
    float sum = s_sum[2 * h] + s_sum[2 * h + 1];
    float sq  = s_sq [2 * h] + s_sq [2 * h + 1];
    float mean = sum * (1.0f / 64.0f);
    float var  = fmaxf(sq * (1.0f / 64.0f) - mean * mean, 0.0f);
    float sd   = sqrtf(var);
    *outp = (val - mean) / (sd * 16.0f);   // sqrt(DIM) = 16
}

// ---------------------------------------------------------------------------
// Main kernel: one CTA per batch sample. 256 threads.
// smem layout (floats):
//   AT [256][57]  : activations TRANSPOSED: AT[c*57 + r]    (stride 57: odd)
//   Qb [49][257]  : Q
//   KV [49][257]  : K, then reused for V
//   S  [4][56][49]: attention scores / probs per head (rows padded to 56)
//
// GEMM thread mapping: tr=tid>>5 (rows tr+8j, j<7), ct=tid&31,
// columns col(cc) = 128*(cc>>2) + 4*ct + (cc&3)  -> two float4 groups.
// ---------------------------------------------------------------------------
#define AT_STRIDE 57
#define QK_STRIDE 257
#define S_HSTRIDE (56 * 49)

#define AT_FLOATS (256 * AT_STRIDE)
#define QK_FLOATS (49 * QK_STRIDE)
#define S_FLOATS  (4 * 56 * 49)
#define SMEM_FLOATS (AT_FLOATS + 2 * QK_FLOATS + S_FLOATS)

#define COL(cc) (128 * ((cc) >> 2) + 4 * ct + ((cc) & 3))

__device__ __forceinline__ void gemm_acc(
    const float* __restrict__ AT, const float* __restrict__ W,
    float acc[7][8], int tr, int ct)
{
    #pragma unroll
    for (int j = 0; j < 7; j++)
        #pragma unroll
        for (int cc = 0; cc < 8; cc++) acc[j][cc] = 0.0f;

    const float4* __restrict__ W4 = (const float4*)W;   // 64 float4 per row

    #pragma unroll 4
    for (int k = 0; k < DIM; k++) {
        float xv[7];
        #pragma unroll
        for (int j = 0; j < 7; j++)
            xv[j] = AT[k * AT_STRIDE + tr + 8 * j];   // warp-broadcast LDS
        float4 wa = __ldg(&W4[k * 64 + ct]);          // cols 4ct..4ct+3
        float4 wb = __ldg(&W4[k * 64 + 32 + ct]);     // cols 128+4ct..
        float wv[8] = {wa.x, wa.y, wa.z, wa.w, wb.x, wb.y, wb.z, wb.w};
        #pragma unroll
        for (int j = 0; j < 7; j++)
            #pragma unroll
            for (int cc = 0; cc < 8; cc++)
                acc[j][cc] = fmaf(xv[j], wv[cc], acc[j][cc]);
    }
}

__global__ __launch_bounds__(256, 1) void irmb_kernel(
    const float* __restrict__ x, float* __restrict__ out)
{
    extern __shared__ float sm[];
    float* AT = sm;
    float* Qb = sm + AT_FLOATS;
    float* KV = Qb + QK_FLOATS;
    float* S  = KV + QK_FLOATS;

    const int b   = blockIdx.x;
    const int tid = threadIdx.x;
    const int ct  = tid & 31;
    const int tr  = tid >> 5;

    const float* xb = x + (size_t)b * (NTOK * DIM);
    float* ob = out + (size_t)b * (NTOK * DIM);

    // ---- load x transposed into AT ----
    for (int i = tid; i < NTOK * DIM; i += 256) {
        int r = i >> 8, c = i & 255;
        AT[c * AT_STRIDE + r] = xb[i];
    }
    __syncthreads();

    float acc[7][8];

    // ---- Q = x @ Wq' + bq' ----
    gemm_acc(AT, g_W[0], acc, tr, ct);
    #pragma unroll
    for (int j = 0; j < 7; j++) {
        int r = tr + 8 * j;
        if (r < NTOK) {
            #pragma unroll
            for (int cc = 0; cc < 8; cc++) {
                int c = COL(cc);
                Qb[r * QK_STRIDE + c] = acc[j][cc] + g_b[0][c];
            }
        }
    }

    // ---- K = x @ Wk' + bk' ----
    gemm_acc(AT, g_W[1], acc, tr, ct);
    #pragma unroll
    for (int j = 0; j < 7; j++) {
        int r = tr + 8 * j;
        if (r < NTOK) {
            #pragma unroll
            for (int cc = 0; cc < 8; cc++) {
                int c = COL(cc);
                KV[r * QK_STRIDE + c] = acc[j][cc] + g_b[1][c];
            }
        }
    }
    __syncthreads();

    // ---- scores S[h][q][kk] = SCALE * <Q[q],K[kk]> ----
    const float SCALE = 0.125f;  // 64^-0.5
    for (int idx = tid; idx < NH * NTOK * NTOK; idx += 256) {
        int h  = idx / (NTOK * NTOK);
        int r2 = idx - h * (NTOK * NTOK);
        int qr = r2 / NTOK;
        int kk = r2 - qr * NTOK;
        const float* qp = &Qb[qr * QK_STRIDE + h * HC];
        const float* kp = &KV[kk * QK_STRIDE + h * HC];
        float a = 0.0f;
        #pragma unroll 16
        for (int c = 0; c < HC; c++) a = fmaf(qp[c], kp[c], a);
        S[h * S_HSTRIDE + qr * NTOK + kk] = a * SCALE;
    }
    __syncthreads();

    // ---- softmax over kk, in place (196 rows) ----
    if (tid < NH * NTOK) {
        int h = tid / NTOK, qr = tid - h * NTOK;
        float* row = &S[h * S_HSTRIDE + qr * NTOK];
        float m = -1e30f;
        for (int kk = 0; kk < NTOK; kk++) m = fmaxf(m, row[kk]);
        float sumv = 0.0f;
        for (int kk = 0; kk < NTOK; kk++) {
            float e = expf(row[kk] - m);
            row[kk] = e;
            sumv += e;
        }
        float inv = 1.0f / sumv;
        for (int kk = 0; kk < NTOK; kk++) row[kk] *= inv;
    }
    __syncthreads();

    // ---- V = (x @ Wv' + bv') * 0.1 + x * 0.95, into KV buffer ----
    gemm_acc(AT, g_W[2], acc, tr, ct);
    #pragma unroll
    for (int j = 0; j < 7; j++) {
        int r = tr + 8 * j;
        if (r < NTOK) {
            #pragma unroll
            for (int cc = 0; cc < 8; cc++) {
                int c = COL(cc);
                float v = acc[j][cc] + g_b[2][c];
                KV[r * QK_STRIDE + c] = v * 0.1f + AT[c * AT_STRIDE + r] * 0.95f;
            }
        }
    }
    __syncthreads();

    // ---- O = P @ V ; xnew = O*0.1 + V*0.95 ; write xnew transposed to AT ----
    {
        float acc2[7][8];
        #pragma unroll
        for (int j = 0; j < 7; j++)
            #pragma unroll
            for (int cc = 0; cc < 8; cc++) acc2[j][cc] = 0.0f;

        const int hsel = ct >> 4;   // head = 2*(cc>>2) + (ct>=16)
        for (int kk = 0; kk < NTOK; kk++) {
            float pv[4][7];
            #pragma unroll
            for (int h = 0; h < 4; h++)
                #pragma unroll
                for (int j = 0; j < 7; j++)
                    pv[h][j] = S[h * S_HSTRIDE + (tr + 8 * j) * NTOK + kk]; // padded rows: in-bounds
            float vv[8];
            #pragma unroll
            for (int cc = 0; cc < 8; cc++)
                vv[cc] = KV[kk * QK_STRIDE + COL(cc)];
            #pragma unroll
            for (int j = 0; j < 7; j++)
                #pragma unroll
                for (int cc = 0; cc < 8; cc++)
                    acc2[j][cc] = fmaf(pv[2 * (cc >> 2) + hsel][j], vv[cc], acc2[j][cc]);
        }
        #pragma unroll
        for (int j = 0; j < 7; j++) {
            int r = tr + 8 * j;
            if (r < NTOK) {
                #pragma unroll
                for (int cc = 0; cc < 8; cc++) {
                    int c = COL(cc);
                    float xnew = acc2[j][cc] * 0.1f + KV[r * QK_STRIDE + c] * 0.95f;
                    AT[c * AT_STRIDE + r] = xnew;
                }
            }
        }
    }
    __syncthreads();

    // ---- FFN in: t1 = x@Wfi'+b ; t2 = t1*0.1 + x*0.95 ;
    //      t3 = (sigmoid(t2)-0.5)*0.1 + t2*0.95 ----
    gemm_acc(AT, g_W[3], acc, tr, ct);
    #pragma unroll
    for (int j = 0; j < 7; j++) {
        int r = tr + 8 * j;
        if (r < NTOK) {
            #pragma unroll
            for (int cc = 0; cc < 8; cc++) {
                int c = COL(cc);
                float t1 = acc[j][cc] + g_b[3][c];
                float t2 = t1 * 0.1f + AT[c * AT_STRIDE + r] * 0.95f;
                float sg = 1.0f / (1.0f + expf(-t2));
                acc[j][cc] = (sg - 0.5f) * 0.1f + t2 * 0.95f;   // t3 in regs
            }
        }
    }
    __syncthreads();   // all reads of old AT complete
    #pragma unroll
    for (int j = 0; j < 7; j++) {
        int r = tr + 8 * j;
        if (r < NTOK) {
            #pragma unroll
            for (int cc = 0; cc < 8; cc++)
                AT[COL(cc) * AT_STRIDE + r] = acc[j][cc];
        }
    }
    __syncthreads();

    // ---- FFN out: t4 = t3@Wfo'+b ; out = t4*0.1 + t3*0.95 ----
    gemm_acc(AT, g_W[4], acc, tr, ct);
    #pragma unroll
    for (int j = 0; j < 7; j++) {
        int r = tr + 8 * j;
        if (r < NTOK) {
            #pragma unroll
            for (int g = 0; g < 2; g++) {
                int c0 = 128 * g + 4 * ct;
                float4 o4;
                o4.x = (acc[j][4*g+0] + g_b[4][c0+0]) * 0.1f + AT[(c0+0) * AT_STRIDE + r] * 0.95f;
                o4.y = (acc[j][4*g+1] + g_b[4][c0+1]) * 0.1f + AT[(c0+1) * AT_STRIDE + r] * 0.95f;
                o4.z = (acc[j][4*g+2] + g_b[4][c0+2]) * 0.1f + AT[(c0+2) * AT_STRIDE + r] * 0.95f;
                o4.w = (acc[j][4*g+3] + g_b[4][c0+3]) * 0.1f + AT[(c0+3) * AT_STRIDE + r] * 0.95f;
                *reinterpret_cast<float4*>(&ob[r * DIM + c0]) = o4;
            }
        }
    }
}

// ---------------------------------------------------------------------------
extern "C" void kernel_launch(void* const* d_in, const int* in_sizes, int n_in,
                              void* d_out, int out_size)
{
    const float* x = (const float*)d_in[0];

    std_kernel<<<5 * DIM + 5, 256>>>(
        (const float*)d_in[1], (const float*)d_in[2],
        (const float*)d_in[3], (const float*)d_in[4],
        (const float*)d_in[5], (const float*)d_in[6],
        (const float*)d_in[7], (const float*)d_in[8],
        (const float*)d_in[9], (const float*)d_in[10]);

    size_t smem = (size_t)SMEM_FLOATS * sizeof(float);   // ~203 KB
    cudaFuncSetAttribute(irmb_kernel,
                         cudaFuncAttributeMaxDynamicSharedMemorySize, (int)smem);
    irmb_kernel<<<NB, 256, smem>>>(x, (float*)d_out);
}